// round 8
// baseline (speedup 1.0000x reference)
#include <cuda_runtime.h>
#include <cuda_fp16.h>
#include <math.h>

#define B 4096
#define T 200
#define D 128
#define U 128

// ---------------- device scratch ----------------
__device__ __align__(128) float g_att[(size_t)T * B];                  // [t][b_orig]
__device__ __align__(128) unsigned g_xproj[(size_t)T * B * 192];       // [t][p_sorted][192] half2
__device__ int g_perm[B];

__device__ __forceinline__ float sigt(float x) {          // sigmoid via tanh.approx (1 MUFU)
    float t;
    asm("tanh.approx.f32 %0, %1;" : "=f"(t) : "f"(0.5f * x));
    return fmaf(0.5f, t, 0.5f);
}
__device__ __forceinline__ float2 sig2(float a, float b) { // paired sigmoid via tanh.approx.f16x2
    __half2 p = __floats2half2_rn(0.5f * a, 0.5f * b);
    unsigned pu = *(unsigned*)&p, r;
    asm("tanh.approx.f16x2 %0, %1;" : "=r"(r) : "r"(pu));
    float2 t = __half22float2(*(__half2*)&r);
    return make_float2(fmaf(0.5f, t.x, 0.5f), fmaf(0.5f, t.y, 0.5f));
}
__device__ __forceinline__ float tanha(float x) {          // tanh.approx.f32 (1 MUFU)
    float t;
    asm("tanh.approx.f32 %0, %1;" : "=f"(t) : "f"(x));
    return t;
}
__device__ __forceinline__ float dicef(float x, float alpha) {
    float p = sigt(x);
    return p * x + alpha * (1.0f - p) * x;
}
__device__ __forceinline__ unsigned packh2(float a, float b) {
    __half2 h = __floats2half2_rn(a, b);
    return *(unsigned*)&h;
}
__device__ __forceinline__ float2 unpackh2(unsigned u) {
    return __half22float2(*(__half2*)&u);
}
__device__ __forceinline__ void mma_f16(float c[4], const unsigned a[4], const unsigned b[2]) {
    asm("mma.sync.aligned.m16n8k16.row.col.f32.f16.f16.f32 "
        "{%0,%1,%2,%3}, {%4,%5,%6,%7}, {%8,%9}, {%0,%1,%2,%3};\n"
        : "+f"(c[0]), "+f"(c[1]), "+f"(c[2]), "+f"(c[3])
        : "r"(a[0]), "r"(a[1]), "r"(a[2]), "r"(a[3]), "r"(b[0]), "r"(b[1]));
}
__device__ __forceinline__ void ldsm_x4(unsigned r[4], unsigned saddr) {
    asm volatile("ldmatrix.sync.aligned.m8n8.x4.shared.b16 {%0,%1,%2,%3}, [%4];"
        : "=r"(r[0]), "=r"(r[1]), "=r"(r[2]), "=r"(r[3]) : "r"(saddr));
}

// ---------------- counting sort ----------------
__global__ __launch_bounds__(512) void k_sort(const int* __restrict__ slen) {
    __shared__ int cnt[256];
    __shared__ int off[256];
    int tid = threadIdx.x;
    if (tid < 256) cnt[tid] = 0;
    __syncthreads();
    for (int b = tid; b < B; b += 512) {
        int L = slen[b]; L = min(max(L, 0), T);
        atomicAdd(&cnt[L], 1);
    }
    __syncthreads();
    if (tid == 0) {
        int acc = 0;
        for (int i = 0; i <= T; i++) { off[i] = acc; acc += cnt[i]; }
    }
    __syncthreads();
    for (int b = tid; b < B; b += 512) {
        int L = slen[b]; L = min(max(L, 0), T);
        int pos = atomicAdd(&off[L], 1);
        g_perm[pos] = b;
    }
}

// ---------------- fused attention + x-projection ----------------
__global__ __launch_bounds__(256) void k_fused(
    const float* __restrict__ x, const float* __restrict__ q_all,
    const int* __restrict__ slen,
    const float* __restrict__ W1, const float* __restrict__ a1,
    const float* __restrict__ W2, const float* __restrict__ a2,
    const float* __restrict__ W3,
    const float* __restrict__ Wu, const float* __restrict__ Wr, const float* __restrict__ Wc)
{
    extern __shared__ unsigned smw[];     // 24576 words: weight staging, then reuse
    unsigned* WtB  = smw;                 // 4096
    unsigned* xk   = smw + 4096;          // 2048
    unsigned* h1h  = smw + 6144;          // 1024: 32 rows x 32 words fp16, chunk-swizzled
    __shared__ unsigned W2h[16 * 32];     // layer-2 weight fp16 B-layout
    __shared__ float a1s[64], a2s[16], W3s[16];
    __shared__ float qs[D], qproj[64];

    int tid = threadIdx.x;
    if (tid < 64) a1s[tid] = a1[tid];
    if (tid < 16) { a2s[tid] = a2[tid]; W3s[tid] = W3[tid]; }
    // W2 -> fp16 B-layout [n=16][kw=32]
    for (int e = tid; e < 512; e += 256) {
        int n = e & 15, kw = e >> 4;
        W2h[n * 32 + (kw ^ ((n & 7) << 2))] = packh2(W2[(2 * kw) * 16 + n], W2[(2 * kw + 1) * 16 + n]);
    }
    // xproj weights -> fp16 B-layout (staging)
    {
        const float* srcs[3] = { Wu, Wr, Wc };
        #pragma unroll
        for (int m = 0; m < 3; m++) {
            const float* S = srcs[m];
            unsigned* Wd = smw + m * 8192;
            for (int e = tid; e < 8192; e += 256) {
                int n = e & 127, kw = e >> 7;
                Wd[n * 64 + (kw ^ ((n & 7) << 2))] = packh2(S[(2 * kw) * 128 + n], S[(2 * kw + 1) * 128 + n]);
            }
        }
    }
    __syncthreads();

    const int w = tid >> 5, lane = tid & 31, g = lane >> 2, tig = lane & 3;
    const int gsw = g << 2;
    const int sub = lane >> 3, r8 = lane & 7;
    const int hi = sub >> 1;
    const int rsel = (sub & 1) * 8 + r8;

    // hoist xproj B-fragments: warp w -> cols w*48 .. w*48+47
    unsigned wb[6][8][2];
    #pragma unroll
    for (int nt = 0; nt < 6; nt++) {
        int col = w * 48 + nt * 8 + g;
        int nb = (col >> 7) * 8192 + (col & 127) * 64;
        #pragma unroll
        for (int s = 0; s < 8; s++) {
            int k0 = (s * 8 + tig) ^ gsw, k1 = (s * 8 + tig + 4) ^ gsw;
            wb[nt][s][0] = smw[nb + k0];
            wb[nt][s][1] = smw[nb + k1];
        }
    }
    // hoist layer-2 B-fragments
    unsigned w2b[2][4][2];
    #pragma unroll
    for (int nt = 0; nt < 2; nt++) {
        int nb2 = (nt * 8 + g) * 32;
        #pragma unroll
        for (int s = 0; s < 4; s++) {
            w2b[nt][s][0] = W2h[nb2 + ((s * 8 + tig) ^ gsw)];
            w2b[nt][s][1] = W2h[nb2 + ((s * 8 + tig + 4) ^ gsw)];
        }
    }
    __syncthreads();   // staging region reusable (WtB/xk/h1h live there)

    unsigned h1sa = (unsigned)__cvta_generic_to_shared(h1h);
    const int r_st = tid >> 3, c_st = tid & 7;   // staging: 8 threads per row
    const int rs_st = (r_st & 7) << 2;

    for (int j = 0; j < 8; j++) {
        int p = blockIdx.x + j * 512;
        int b = g_perm[p];
        int L = slen[b]; L = min(max(L, 0), T);
        if (L == 0) continue;

        if (tid < D) qs[tid] = q_all[(size_t)b * D + tid];
        __syncthreads();

        for (int e = tid; e < 4096; e += 256) {
            int n = e & 63, kw = e >> 6;
            int d0 = 2 * kw, d1 = 2 * kw + 1;
            float v0 = W1[(128 + d0) * 64 + n] - W1[(256 + d0) * 64 + n] + qs[d0] * W1[(384 + d0) * 64 + n];
            float v1 = W1[(128 + d1) * 64 + n] - W1[(256 + d1) * 64 + n] + qs[d1] * W1[(384 + d1) * 64 + n];
            WtB[n * 64 + (kw ^ ((n & 7) << 2))] = packh2(v0, v1);
        }
        if (tid < 64) {
            float acc = 0.0f;
            for (int d = 0; d < D; d++)
                acc += qs[d] * (W1[d * 64 + tid] + W1[(256 + d) * 64 + tid]);
            qproj[tid] = acc;
        }

        // prefetch tile 0 into regs
        float4 xa[4];
        {
            if (r_st < L) {
                const float4* xp = (const float4*)&x[((size_t)b * T + r_st) * D + c_st * 16];
                #pragma unroll
                for (int q4 = 0; q4 < 4; q4++) xa[q4] = xp[q4];
            } else {
                #pragma unroll
                for (int q4 = 0; q4 < 4; q4++) xa[q4] = make_float4(0.f, 0.f, 0.f, 0.f);
            }
        }
        __syncthreads();

        for (int t0 = 0; t0 < L; t0 += 32) {
            // store staged regs -> xk (word-swizzled fp16)
            {
                unsigned wv[8];
                #pragma unroll
                for (int q4 = 0; q4 < 4; q4++) {
                    wv[q4 * 2 + 0] = packh2(xa[q4].x, xa[q4].y);
                    wv[q4 * 2 + 1] = packh2(xa[q4].z, xa[q4].w);
                }
                int blockbase = r_st * 64 + ((c_st * 8) ^ (rs_st & 24));
                int lo = rs_st & 4;
                *(uint4*)&xk[blockbase + lo]       = make_uint4(wv[0], wv[1], wv[2], wv[3]);
                *(uint4*)&xk[blockbase + (lo ^ 4)] = make_uint4(wv[4], wv[5], wv[6], wv[7]);
            }
            __syncthreads();   // xk ready

            // prefetch next tile into regs (hidden behind MMA passes)
            {
                int tnx = t0 + 32 + r_st;
                if (tnx < L) {
                    const float4* xp = (const float4*)&x[((size_t)b * T + tnx) * D + c_st * 16];
                    #pragma unroll
                    for (int q4 = 0; q4 < 4; q4++) xa[q4] = xp[q4];
                } else {
                    #pragma unroll
                    for (int q4 = 0; q4 < 4; q4++) xa[q4] = make_float4(0.f, 0.f, 0.f, 0.f);
                }
            }

            // ---- pass 1: attention layer-1, dice -> packed fp16 h1h ----
            {
                float acca[2][4];
                float p0 = qproj[w * 8 + 2 * tig], p1 = qproj[w * 8 + 2 * tig + 1];
                acca[0][0] = p0; acca[0][1] = p1; acca[0][2] = p0; acca[0][3] = p1;
                acca[1][0] = p0; acca[1][1] = p1; acca[1][2] = p0; acca[1][3] = p1;
                int nbatt = (w * 8 + g) * 64;
                #pragma unroll
                for (int s = 0; s < 8; s++) {
                    int k0 = (s * 8 + tig) ^ gsw, k1 = (s * 8 + tig + 4) ^ gsw;
                    unsigned a[2][4], bb[2];
                    #pragma unroll
                    for (int mt = 0; mt < 2; mt++) {
                        int r0 = mt * 16 + g;
                        a[mt][0] = xk[r0 * 64 + k0];
                        a[mt][1] = xk[(r0 + 8) * 64 + k0];
                        a[mt][2] = xk[r0 * 64 + k1];
                        a[mt][3] = xk[(r0 + 8) * 64 + k1];
                    }
                    bb[0] = WtB[nbatt + k0];
                    bb[1] = WtB[nbatt + k1];
                    mma_f16(acca[0], a[0], bb);
                    mma_f16(acca[1], a[1], bb);
                }
                int col = w * 8 + 2 * tig;
                float al0 = a1s[col], al1 = a1s[col + 1];
                int chsw = ((w ^ g) << 2) + tig;
                #pragma unroll
                for (int mt = 0; mt < 2; mt++) {
                    int r0 = mt * 16 + g;
                    h1h[r0 * 32 + chsw]       = packh2(dicef(acca[mt][0], al0), dicef(acca[mt][1], al1));
                    h1h[(r0 + 8) * 32 + chsw] = packh2(dicef(acca[mt][2], al0), dicef(acca[mt][3], al1));
                }
            }

            // ---- pass 2: x-projection, direct STG to g_xproj ----
            {
                float acc[2][6][4];
                #pragma unroll
                for (int mt = 0; mt < 2; mt++)
                    #pragma unroll
                    for (int nt = 0; nt < 6; nt++)
                        #pragma unroll
                        for (int k = 0; k < 4; k++) acc[mt][nt][k] = 0.0f;

                #pragma unroll
                for (int s = 0; s < 8; s++) {
                    int k0 = (s * 8 + tig) ^ gsw, k1 = (s * 8 + tig + 4) ^ gsw;
                    unsigned a[2][4];
                    #pragma unroll
                    for (int mt = 0; mt < 2; mt++) {
                        int r0 = mt * 16 + g;
                        a[mt][0] = xk[r0 * 64 + k0];
                        a[mt][1] = xk[(r0 + 8) * 64 + k0];
                        a[mt][2] = xk[r0 * 64 + k1];
                        a[mt][3] = xk[(r0 + 8) * 64 + k1];
                    }
                    #pragma unroll
                    for (int nt = 0; nt < 6; nt++) {
                        mma_f16(acc[0][nt], a[0], wb[nt][s]);
                        mma_f16(acc[1][nt], a[1], wb[nt][s]);
                    }
                }
                #pragma unroll
                for (int mt = 0; mt < 2; mt++) {
                    int trow0 = t0 + mt * 16 + g;
                    bool v0 = trow0 < L, v1 = (trow0 + 8) < L;
                    size_t gb0 = ((size_t)trow0 * B + p) * 192;
                    size_t gb1 = ((size_t)(trow0 + 8) * B + p) * 192;
                    #pragma unroll
                    for (int nt = 0; nt < 6; nt++) {
                        int c2 = w * 24 + nt * 4 + tig;
                        if (v0) g_xproj[gb0 + c2] = packh2(acc[mt][nt][0], acc[mt][nt][1]);
                        if (v1) g_xproj[gb1 + c2] = packh2(acc[mt][nt][2], acc[mt][nt][3]);
                    }
                }
            }
            __syncthreads();   // h1h ready; xk fully consumed

            if (w < 2) {
                // ---- layers 2+3 via MMA: warps 0-1, m-tile of 16 rows each ----
                int m0 = w * 16;
                float acc2[2][4];
                #pragma unroll
                for (int nt = 0; nt < 2; nt++)
                    #pragma unroll
                    for (int k = 0; k < 4; k++) acc2[nt][k] = 0.0f;
                unsigned baseH = h1sa + (unsigned)((m0 + rsel) * 128);
                #pragma unroll
                for (int s = 0; s < 4; s++) {
                    unsigned av[4];
                    ldsm_x4(av, baseH + (unsigned)((((2 * s + hi) ^ r8) << 4)));
                    mma_f16(acc2[0], av, w2b[0][s]);
                    mma_f16(acc2[1], av, w2b[1][s]);
                }
                float v0 = 0.0f, v1 = 0.0f;
                #pragma unroll
                for (int nt = 0; nt < 2; nt++) {
                    int c0 = nt * 8 + 2 * tig;
                    float wa = W3s[c0], wb3 = W3s[c0 + 1];
                    float aa = a2s[c0], ab = a2s[c0 + 1];
                    v0 += dicef(acc2[nt][0], aa) * wa + dicef(acc2[nt][1], ab) * wb3;
                    v1 += dicef(acc2[nt][2], aa) * wa + dicef(acc2[nt][3], ab) * wb3;
                }
                v0 += __shfl_xor_sync(0xffffffffu, v0, 1);
                v0 += __shfl_xor_sync(0xffffffffu, v0, 2);
                v1 += __shfl_xor_sync(0xffffffffu, v1, 1);
                v1 += __shfl_xor_sync(0xffffffffu, v1, 2);
                if (tig == 0) {
                    int trow0 = t0 + m0 + g;
                    int trow1 = trow0 + 8;
                    if (trow0 < L) g_att[(size_t)trow0 * B + b] = sigt(v0);
                    if (trow1 < L) g_att[(size_t)trow1 * B + b] = sigt(v1);
                }
            }
        }
        __syncthreads();   // h1h consumed before next b's passes
    }
}

// ---------------- AUGRU scan ----------------
__global__ __launch_bounds__(256) void k_augru(
    const int* __restrict__ slen,
    const float* __restrict__ Wu, const float* __restrict__ Wr, const float* __restrict__ Wc,
    float* __restrict__ out)
{
    extern __shared__ unsigned smw[];
    unsigned* hT  = smw + 24576;
    unsigned* rhT = smw + 26624;
    __shared__ int   Ls[32];
    __shared__ int   bis[32];
    __shared__ float atts[2][32];
    __shared__ int   LmaxS;

    int tid = threadIdx.x;

    for (int e = tid; e < 8192; e += 256) {
        int n = e & 127, kw = e >> 7;
        int sw = n * 64 + (kw ^ ((n & 7) << 2));
        smw[sw]         = packh2(Wu[16384 + (2 * kw) * 128 + n], Wu[16384 + (2 * kw + 1) * 128 + n]);
        smw[8192 + sw]  = packh2(Wr[16384 + (2 * kw) * 128 + n], Wr[16384 + (2 * kw + 1) * 128 + n]);
        smw[16384 + sw] = packh2(Wc[16384 + (2 * kw) * 128 + n], Wc[16384 + (2 * kw + 1) * 128 + n]);
    }
    for (int e = tid; e < 4096; e += 256) hT[e] = 0u;
    if (tid < 32) {
        int b = g_perm[blockIdx.x * 32 + tid];
        bis[tid] = b;
        int L = slen[b]; L = min(max(L, 0), T);
        Ls[tid] = L;
    }
    __syncthreads();
    if (tid == 0) { int m = 0; for (int i = 0; i < 32; i++) m = max(m, Ls[i]); LmaxS = m; }

    const int w = tid >> 5, lane = tid & 31, g = lane >> 2, tig = lane & 3;
    const int gsw = g << 2;
    const int n0w = w * 16;

    unsigned wu[2][8][2], wr[2][8][2], wc[2][8][2];
    #pragma unroll
    for (int nt = 0; nt < 2; nt++) {
        int nb = (n0w + nt * 8 + g) * 64;
        #pragma unroll
        for (int s = 0; s < 8; s++) {
            int k0 = (s * 8 + tig) ^ gsw, k1 = (s * 8 + tig + 4) ^ gsw;
            wu[nt][s][0] = smw[nb + k0];          wu[nt][s][1] = smw[nb + k1];
            wr[nt][s][0] = smw[8192 + nb + k0];   wr[nt][s][1] = smw[8192 + nb + k1];
            wc[nt][s][0] = smw[16384 + nb + k0];  wc[nt][s][1] = smw[16384 + nb + k1];
        }
    }
    __syncthreads();
    const int Lmax = LmaxS;
    const int p0 = blockIdx.x * 32;

    const int sub = lane >> 3, r8 = lane & 7;
    const int hi = sub >> 1;
    const int rsel = (sub & 1) * 8 + r8;
    unsigned hTsa = (unsigned)__cvta_generic_to_shared(hT);
    unsigned baseA[2];
    baseA[0] = hTsa + (unsigned)(rsel * 256);
    baseA[1] = hTsa + (unsigned)((16 + rsel) * 256);

    int stoff[2];
    #pragma unroll
    for (int nt = 0; nt < 2; nt++) stoff[nt] = (((w * 2 + nt) ^ g) << 2) + tig;

    int myL[4];
    #pragma unroll
    for (int ri = 0; ri < 4; ri++) myL[ri] = Ls[(ri >> 1) * 16 + (ri & 1) * 8 + g];

    float hm[2][2][4];
    #pragma unroll
    for (int mt = 0; mt < 2; mt++)
        #pragma unroll
        for (int nt = 0; nt < 2; nt++)
            #pragma unroll
            for (int k = 0; k < 4; k++) hm[mt][nt][k] = 0.0f;

    // preload all-gate x-projections for t=0 and atts[0]
    unsigned xal[2][2][2][3];
    {
        #pragma unroll
        for (int mt = 0; mt < 2; mt++)
            #pragma unroll
            for (int half = 0; half < 2; half++) {
                size_t rb = ((size_t)p0 + mt * 16 + half * 8 + g) * 192 + w * 8 + tig;
                #pragma unroll
                for (int nt = 0; nt < 2; nt++) {
                    xal[mt][half][nt][0] = g_xproj[rb + nt * 4];
                    xal[mt][half][nt][1] = g_xproj[rb + 64 + nt * 4];
                    xal[mt][half][nt][2] = g_xproj[rb + 128 + nt * 4];
                }
            }
        if (tid < 32) atts[0][tid] = g_att[(size_t)0 * B + bis[tid]];
    }
    __syncthreads();

    for (int t = 0; t < Lmax; t++) {
        int cur = t & 1, nxt = cur ^ 1;
        int tn = min(t + 1, T - 1);

        unsigned xaln[2][2][2][3];
        {
            size_t tbn = (size_t)tn * B + p0;
            #pragma unroll
            for (int mt = 0; mt < 2; mt++)
                #pragma unroll
                for (int half = 0; half < 2; half++) {
                    size_t rbn = (tbn + mt * 16 + half * 8 + g) * 192 + w * 8 + tig;
                    #pragma unroll
                    for (int nt = 0; nt < 2; nt++) {
                        xaln[mt][half][nt][0] = g_xproj[rbn + nt * 4];
                        xaln[mt][half][nt][1] = g_xproj[rbn + 64 + nt * 4];
                        xaln[mt][half][nt][2] = g_xproj[rbn + 128 + nt * 4];
                    }
                }
        }
        float attn_v = 0.0f;
        if (tid < 32) attn_v = g_att[(size_t)tn * B + bis[tid]];

        // phase A
        float accU[2][2][4], accR[2][2][4];
        #pragma unroll
        for (int mt = 0; mt < 2; mt++)
            #pragma unroll
            for (int nt = 0; nt < 2; nt++)
                #pragma unroll
                for (int k = 0; k < 4; k++) { accU[mt][nt][k] = 0.0f; accR[mt][nt][k] = 0.0f; }

        #pragma unroll
        for (int s = 0; s < 8; s++) {
            unsigned choff = (unsigned)((((2 * s + hi) ^ r8) << 4));
            unsigned ah[2][4];
            ldsm_x4(ah[0], baseA[0] + choff);
            ldsm_x4(ah[1], baseA[1] + choff);
            #pragma unroll
            for (int nt = 0; nt < 2; nt++)
                #pragma unroll
                for (int mt = 0; mt < 2; mt++) {
                    mma_f16(accU[mt][nt], ah[mt], wu[nt][s]);
                    mma_f16(accR[mt][nt], ah[mt], wr[nt][s]);
                }
        }

        // gates u, r (paired f16x2 MUFU); store r*h
        float uu[2][2][4];
        #pragma unroll
        for (int mt = 0; mt < 2; mt++)
            #pragma unroll
            for (int nt = 0; nt < 2; nt++)
                #pragma unroll
                for (int half = 0; half < 2; half++) {
                    int row = mt * 16 + half * 8 + g;
                    float2 xu = unpackh2(xal[mt][half][nt][0]);
                    float2 xr = unpackh2(xal[mt][half][nt][1]);
                    float2 uv = sig2(accU[mt][nt][half * 2 + 0] + xu.x, accU[mt][nt][half * 2 + 1] + xu.y);
                    float2 rv = sig2(accR[mt][nt][half * 2 + 0] + xr.x, accR[mt][nt][half * 2 + 1] + xr.y);
                    uu[mt][nt][half * 2 + 0] = uv.x;
                    uu[mt][nt][half * 2 + 1] = uv.y;
                    rhT[row * 64 + stoff[nt]] =
                        packh2(rv.x * hm[mt][nt][half * 2 + 0], rv.y * hm[mt][nt][half * 2 + 1]);
                }
        if (tid < 32) atts[nxt][tid] = attn_v;
        __syncthreads();

        // phase B
        float accC[2][2][4];
        #pragma unroll
        for (int mt = 0; mt < 2; mt++)
            #pragma unroll
            for (int nt = 0; nt < 2; nt++)
                #pragma unroll
                for (int half = 0; half < 2; half++) {
                    float2 xc = unpackh2(xal[mt][half][nt][2]);
                    accC[mt][nt][half * 2 + 0] = xc.x;
                    accC[mt][nt][half * 2 + 1] = xc.y;
                }

        #pragma unroll
        for (int s = 0; s < 8; s++) {
            unsigned choff = (unsigned)((((2 * s + hi) ^ r8) << 4)) + 8192u;
            unsigned ar[2][4];
            ldsm_x4(ar[0], baseA[0] + choff);
            ldsm_x4(ar[1], baseA[1] + choff);
            #pragma unroll
            for (int nt = 0; nt < 2; nt++)
                #pragma unroll
                for (int mt = 0; mt < 2; mt++)
                    mma_f16(accC[mt][nt], ar[mt], wc[nt][s]);
        }

        // h update (tanh.approx.f32 candidate) + refresh hT
        #pragma unroll
        for (int mt = 0; mt < 2; mt++)
            #pragma unroll
            for (int nt = 0; nt < 2; nt++)
                #pragma unroll
                for (int half = 0; half < 2; half++) {
                    int ri = mt * 2 + half;
                    int row = mt * 16 + half * 8 + g;
                    if (t < myL[ri]) {
                        float a_att = atts[cur][row];
                        float c0 = tanha(accC[mt][nt][half * 2 + 0]);
                        float c1 = tanha(accC[mt][nt][half * 2 + 1]);
                        float ut0 = uu[mt][nt][half * 2 + 0] * a_att;
                        float ut1 = uu[mt][nt][half * 2 + 1] * a_att;
                        hm[mt][nt][half * 2 + 0] += ut0 * (c0 - hm[mt][nt][half * 2 + 0]);
                        hm[mt][nt][half * 2 + 1] += ut1 * (c1 - hm[mt][nt][half * 2 + 1]);
                    }
                    hT[row * 64 + stoff[nt]] =
                        packh2(hm[mt][nt][half * 2 + 0], hm[mt][nt][half * 2 + 1]);
                }
        __syncthreads();

        #pragma unroll
        for (int mt = 0; mt < 2; mt++)
            #pragma unroll
            for (int half = 0; half < 2; half++)
                #pragma unroll
                for (int nt = 0; nt < 2; nt++)
                    #pragma unroll
                    for (int gt = 0; gt < 3; gt++)
                        xal[mt][half][nt][gt] = xaln[mt][half][nt][gt];
    }

    #pragma unroll
    for (int mt = 0; mt < 2; mt++)
        #pragma unroll
        for (int nt = 0; nt < 2; nt++) {
            int col = n0w + nt * 8 + tig * 2;
            #pragma unroll
            for (int half = 0; half < 2; half++) {
                int row = mt * 16 + half * 8 + g;
                size_t base = (size_t)bis[row] * U + col;
                out[base]     = hm[mt][nt][half * 2 + 0];
                out[base + 1] = hm[mt][nt][half * 2 + 1];
            }
        }
}

// ---------------- launch ----------------
extern "C" void kernel_launch(void* const* d_in, const int* in_sizes, int n_in,
                              void* d_out, int out_size)
{
    const float* x    = (const float*)d_in[0];
    const float* q    = (const float*)d_in[1];
    const int*   slen = (const int*)d_in[2];
    const float* W1   = (const float*)d_in[3];
    const float* a1   = (const float*)d_in[4];
    const float* W2   = (const float*)d_in[5];
    const float* a2   = (const float*)d_in[6];
    const float* W3   = (const float*)d_in[7];
    const float* Wu   = (const float*)d_in[8];
    const float* Wr   = (const float*)d_in[9];
    const float* Wc   = (const float*)d_in[10];
    float* out = (float*)d_out;

    const int FUSED_SMEM = 24576 * 4;
    const int AUGRU_SMEM = 28672 * 4;

    cudaFuncSetAttribute(k_fused, cudaFuncAttributeMaxDynamicSharedMemorySize, FUSED_SMEM);
    cudaFuncSetAttribute(k_augru, cudaFuncAttributeMaxDynamicSharedMemorySize, AUGRU_SMEM);

    k_sort<<<1, 512>>>(slen);
    k_fused<<<512, 256, FUSED_SMEM>>>(x, q, slen, W1, a1, W2, a2, W3, Wu, Wr, Wc);
    k_augru<<<B / 32, 256, AUGRU_SMEM>>>(slen, Wu, Wr, Wc, out);
}

// round 9
// speedup vs baseline: 1.1545x; 1.1545x over previous
#include <cuda_runtime.h>
#include <cuda_fp16.h>
#include <math.h>

#define B 4096
#define T 200
#define D 128
#define U 128

// ---------------- device scratch ----------------
__device__ __align__(128) float g_att[(size_t)T * B];                  // [t][b_orig]
__device__ __align__(128) unsigned g_xproj[(size_t)T * B * 192];       // [t][p_sorted][192] half2 (permuted cols)
__device__ int g_perm[B];

__device__ __forceinline__ float sigt(float x) {          // sigmoid via tanh.approx (1 MUFU)
    float t;
    asm("tanh.approx.f32 %0, %1;" : "=f"(t) : "f"(0.5f * x));
    return fmaf(0.5f, t, 0.5f);
}
__device__ __forceinline__ float2 sig2(float a, float b) { // paired sigmoid via tanh.approx.f16x2
    __half2 p = __floats2half2_rn(0.5f * a, 0.5f * b);
    unsigned pu = *(unsigned*)&p, r;
    asm("tanh.approx.f16x2 %0, %1;" : "=r"(r) : "r"(pu));
    float2 t = __half22float2(*(__half2*)&r);
    return make_float2(fmaf(0.5f, t.x, 0.5f), fmaf(0.5f, t.y, 0.5f));
}
__device__ __forceinline__ float tanha(float x) {          // tanh.approx.f32 (1 MUFU)
    float t;
    asm("tanh.approx.f32 %0, %1;" : "=f"(t) : "f"(x));
    return t;
}
__device__ __forceinline__ float dicef(float x, float alpha) {
    float p = sigt(x);
    return p * x + alpha * (1.0f - p) * x;
}
__device__ __forceinline__ unsigned packh2(float a, float b) {
    __half2 h = __floats2half2_rn(a, b);
    return *(unsigned*)&h;
}
__device__ __forceinline__ float2 unpackh2(unsigned u) {
    return __half22float2(*(__half2*)&u);
}
__device__ __forceinline__ void mma_f16(float c[4], const unsigned a[4], const unsigned b[2]) {
    asm("mma.sync.aligned.m16n8k16.row.col.f32.f16.f16.f32 "
        "{%0,%1,%2,%3}, {%4,%5,%6,%7}, {%8,%9}, {%0,%1,%2,%3};\n"
        : "+f"(c[0]), "+f"(c[1]), "+f"(c[2]), "+f"(c[3])
        : "r"(a[0]), "r"(a[1]), "r"(a[2]), "r"(a[3]), "r"(b[0]), "r"(b[1]));
}
__device__ __forceinline__ void ldsm_x4(unsigned r[4], unsigned saddr) {
    asm volatile("ldmatrix.sync.aligned.m8n8.x4.shared.b16 {%0,%1,%2,%3}, [%4];"
        : "=r"(r[0]), "=r"(r[1]), "=r"(r[2]), "=r"(r[3]) : "r"(saddr));
}

// ---------------- counting sort ----------------
__global__ __launch_bounds__(512) void k_sort(const int* __restrict__ slen) {
    __shared__ int cnt[256];
    __shared__ int off[256];
    int tid = threadIdx.x;
    if (tid < 256) cnt[tid] = 0;
    __syncthreads();
    for (int b = tid; b < B; b += 512) {
        int L = slen[b]; L = min(max(L, 0), T);
        atomicAdd(&cnt[L], 1);
    }
    __syncthreads();
    if (tid == 0) {
        int acc = 0;
        for (int i = 0; i <= T; i++) { off[i] = acc; acc += cnt[i]; }
    }
    __syncthreads();
    for (int b = tid; b < B; b += 512) {
        int L = slen[b]; L = min(max(L, 0), T);
        int pos = atomicAdd(&off[L], 1);
        g_perm[pos] = b;
    }
}

// ---------------- fused attention + x-projection ----------------
__global__ __launch_bounds__(256) void k_fused(
    const float* __restrict__ x, const float* __restrict__ q_all,
    const int* __restrict__ slen,
    const float* __restrict__ W1, const float* __restrict__ a1,
    const float* __restrict__ W2, const float* __restrict__ a2,
    const float* __restrict__ W3,
    const float* __restrict__ Wu, const float* __restrict__ Wr, const float* __restrict__ Wc)
{
    extern __shared__ unsigned smw[];     // 24576 words: weight staging, then reuse
    unsigned* WtB  = smw;                 // 4096
    unsigned* xk   = smw + 4096;          // 2048
    unsigned* xout = smw + 6144;          // 6272 (rows of 196, 192 used)
    unsigned* h1h  = smw + 12416;         // 1024: 32 rows x 32 words fp16, chunk-swizzled
    __shared__ unsigned W2h[16 * 32];
    __shared__ float a1s[64], a2s[16], W3s[16];
    __shared__ float qs[D], qproj[64];

    int tid = threadIdx.x;
    if (tid < 64) a1s[tid] = a1[tid];
    if (tid < 16) { a2s[tid] = a2[tid]; W3s[tid] = W3[tid]; }
    for (int e = tid; e < 512; e += 256) {
        int n = e & 15, kw = e >> 4;
        W2h[n * 32 + (kw ^ ((n & 7) << 2))] = packh2(W2[(2 * kw) * 16 + n], W2[(2 * kw + 1) * 16 + n]);
    }
    {
        const float* srcs[3] = { Wu, Wr, Wc };
        #pragma unroll
        for (int m = 0; m < 3; m++) {
            const float* S = srcs[m];
            unsigned* Wd = smw + m * 8192;
            for (int e = tid; e < 8192; e += 256) {
                int n = e & 127, kw = e >> 7;
                Wd[n * 64 + (kw ^ ((n & 7) << 2))] = packh2(S[(2 * kw) * 128 + n], S[(2 * kw + 1) * 128 + n]);
            }
        }
    }
    __syncthreads();

    const int w = tid >> 5, lane = tid & 31, g = lane >> 2, tig = lane & 3;
    const int gsw = g << 2;
    const int sub = lane >> 3, r8 = lane & 7;
    const int hi = sub >> 1;
    const int rsel = (sub & 1) * 8 + r8;

    unsigned wb[6][8][2];
    #pragma unroll
    for (int nt = 0; nt < 6; nt++) {
        int col = w * 48 + nt * 8 + g;
        int nb = (col >> 7) * 8192 + (col & 127) * 64;
        #pragma unroll
        for (int s = 0; s < 8; s++) {
            int k0 = (s * 8 + tig) ^ gsw, k1 = (s * 8 + tig + 4) ^ gsw;
            wb[nt][s][0] = smw[nb + k0];
            wb[nt][s][1] = smw[nb + k1];
        }
    }
    unsigned w2b[2][4][2];
    #pragma unroll
    for (int nt = 0; nt < 2; nt++) {
        int nb2 = (nt * 8 + g) * 32;
        #pragma unroll
        for (int s = 0; s < 4; s++) {
            w2b[nt][s][0] = W2h[nb2 + ((s * 8 + tig) ^ gsw)];
            w2b[nt][s][1] = W2h[nb2 + ((s * 8 + tig + 4) ^ gsw)];
        }
    }
    // permuted xout column index per (nt): reader layout c' = (wr*4+tigr)*6 + gate*2 + ntr
    int cperm[6];
    #pragma unroll
    for (int nt = 0; nt < 6; nt++) {
        int W = w * 24 + nt * 4 + tig;       // old global word index
        int gate = W >> 6, k = W & 63;
        cperm[nt] = ((k >> 3) * 4 + (k & 3)) * 6 + gate * 2 + ((k >> 2) & 1);
    }
    __syncthreads();   // staging region reusable

    unsigned h1sa = (unsigned)__cvta_generic_to_shared(h1h);
    const int r_st = tid >> 3, c_st = tid & 7;
    const int rs_st = (r_st & 7) << 2;

    for (int j = 0; j < 8; j++) {
        int p = blockIdx.x + j * 512;
        int b = g_perm[p];
        int L = slen[b]; L = min(max(L, 0), T);
        if (L == 0) continue;

        if (tid < D) qs[tid] = q_all[(size_t)b * D + tid];
        __syncthreads();

        for (int e = tid; e < 4096; e += 256) {
            int n = e & 63, kw = e >> 6;
            int d0 = 2 * kw, d1 = 2 * kw + 1;
            float v0 = W1[(128 + d0) * 64 + n] - W1[(256 + d0) * 64 + n] + qs[d0] * W1[(384 + d0) * 64 + n];
            float v1 = W1[(128 + d1) * 64 + n] - W1[(256 + d1) * 64 + n] + qs[d1] * W1[(384 + d1) * 64 + n];
            WtB[n * 64 + (kw ^ ((n & 7) << 2))] = packh2(v0, v1);
        }
        if (tid < 64) {
            float acc = 0.0f;
            for (int d = 0; d < D; d++)
                acc += qs[d] * (W1[d * 64 + tid] + W1[(256 + d) * 64 + tid]);
            qproj[tid] = acc;
        }

        // prefetch tile 0 into regs
        float4 xa[4];
        if (r_st < L) {
            const float4* xp = (const float4*)&x[((size_t)b * T + r_st) * D + c_st * 16];
            #pragma unroll
            for (int q4 = 0; q4 < 4; q4++) xa[q4] = xp[q4];
        } else {
            #pragma unroll
            for (int q4 = 0; q4 < 4; q4++) xa[q4] = make_float4(0.f, 0.f, 0.f, 0.f);
        }
        __syncthreads();

        for (int t0 = 0; t0 < L; t0 += 32) {
            // staged regs -> xk
            {
                unsigned wv[8];
                #pragma unroll
                for (int q4 = 0; q4 < 4; q4++) {
                    wv[q4 * 2 + 0] = packh2(xa[q4].x, xa[q4].y);
                    wv[q4 * 2 + 1] = packh2(xa[q4].z, xa[q4].w);
                }
                int blockbase = r_st * 64 + ((c_st * 8) ^ (rs_st & 24));
                int lo = rs_st & 4;
                *(uint4*)&xk[blockbase + lo]       = make_uint4(wv[0], wv[1], wv[2], wv[3]);
                *(uint4*)&xk[blockbase + (lo ^ 4)] = make_uint4(wv[4], wv[5], wv[6], wv[7]);
            }
            __syncthreads();   // xk ready

            // prefetch next tile (hidden behind MMA passes)
            {
                int tnx = t0 + 32 + r_st;
                if (tnx < L) {
                    const float4* xp = (const float4*)&x[((size_t)b * T + tnx) * D + c_st * 16];
                    #pragma unroll
                    for (int q4 = 0; q4 < 4; q4++) xa[q4] = xp[q4];
                } else {
                    #pragma unroll
                    for (int q4 = 0; q4 < 4; q4++) xa[q4] = make_float4(0.f, 0.f, 0.f, 0.f);
                }
            }

            // ---- pass 1: attention layer-1, dice -> packed fp16 h1h ----
            {
                float acca[2][4];
                float p0 = qproj[w * 8 + 2 * tig], p1 = qproj[w * 8 + 2 * tig + 1];
                acca[0][0] = p0; acca[0][1] = p1; acca[0][2] = p0; acca[0][3] = p1;
                acca[1][0] = p0; acca[1][1] = p1; acca[1][2] = p0; acca[1][3] = p1;
                int nbatt = (w * 8 + g) * 64;
                #pragma unroll
                for (int s = 0; s < 8; s++) {
                    int k0 = (s * 8 + tig) ^ gsw, k1 = (s * 8 + tig + 4) ^ gsw;
                    unsigned a[2][4], bb[2];
                    #pragma unroll
                    for (int mt = 0; mt < 2; mt++) {
                        int r0 = mt * 16 + g;
                        a[mt][0] = xk[r0 * 64 + k0];
                        a[mt][1] = xk[(r0 + 8) * 64 + k0];
                        a[mt][2] = xk[r0 * 64 + k1];
                        a[mt][3] = xk[(r0 + 8) * 64 + k1];
                    }
                    bb[0] = WtB[nbatt + k0];
                    bb[1] = WtB[nbatt + k1];
                    mma_f16(acca[0], a[0], bb);
                    mma_f16(acca[1], a[1], bb);
                }
                int col = w * 8 + 2 * tig;
                float al0 = a1s[col], al1 = a1s[col + 1];
                int chsw = ((w ^ g) << 2) + tig;
                #pragma unroll
                for (int mt = 0; mt < 2; mt++) {
                    int r0 = mt * 16 + g;
                    h1h[r0 * 32 + chsw]       = packh2(dicef(acca[mt][0], al0), dicef(acca[mt][1], al1));
                    h1h[(r0 + 8) * 32 + chsw] = packh2(dicef(acca[mt][2], al0), dicef(acca[mt][3], al1));
                }
            }

            // ---- pass 2: x-projection -> xout (permuted cols) ----
            {
                float acc[2][6][4];
                #pragma unroll
                for (int mt = 0; mt < 2; mt++)
                    #pragma unroll
                    for (int nt = 0; nt < 6; nt++)
                        #pragma unroll
                        for (int k = 0; k < 4; k++) acc[mt][nt][k] = 0.0f;

                #pragma unroll
                for (int s = 0; s < 8; s++) {
                    int k0 = (s * 8 + tig) ^ gsw, k1 = (s * 8 + tig + 4) ^ gsw;
                    unsigned a[2][4];
                    #pragma unroll
                    for (int mt = 0; mt < 2; mt++) {
                        int r0 = mt * 16 + g;
                        a[mt][0] = xk[r0 * 64 + k0];
                        a[mt][1] = xk[(r0 + 8) * 64 + k0];
                        a[mt][2] = xk[r0 * 64 + k1];
                        a[mt][3] = xk[(r0 + 8) * 64 + k1];
                    }
                    #pragma unroll
                    for (int nt = 0; nt < 6; nt++) {
                        mma_f16(acc[0][nt], a[0], wb[nt][s]);
                        mma_f16(acc[1][nt], a[1], wb[nt][s]);
                    }
                }
                #pragma unroll
                for (int mt = 0; mt < 2; mt++)
                    #pragma unroll
                    for (int nt = 0; nt < 6; nt++) {
                        int cp = cperm[nt];
                        xout[(mt * 16 + g) * 196 + cp]     = packh2(acc[mt][nt][0], acc[mt][nt][1]);
                        xout[(mt * 16 + 8 + g) * 196 + cp] = packh2(acc[mt][nt][2], acc[mt][nt][3]);
                    }
            }
            __syncthreads();

            if (w < 2) {
                // ---- layers 2+3 via MMA ----
                int m0 = w * 16;
                float acc2[2][4];
                #pragma unroll
                for (int nt = 0; nt < 2; nt++)
                    #pragma unroll
                    for (int k = 0; k < 4; k++) acc2[nt][k] = 0.0f;
                unsigned baseH = h1sa + (unsigned)((m0 + rsel) * 128);
                #pragma unroll
                for (int s = 0; s < 4; s++) {
                    unsigned av[4];
                    ldsm_x4(av, baseH + (unsigned)((((2 * s + hi) ^ r8) << 4)));
                    mma_f16(acc2[0], av, w2b[0][s]);
                    mma_f16(acc2[1], av, w2b[1][s]);
                }
                float v0 = 0.0f, v1 = 0.0f;
                #pragma unroll
                for (int nt = 0; nt < 2; nt++) {
                    int c0 = nt * 8 + 2 * tig;
                    float wa = W3s[c0], wb3 = W3s[c0 + 1];
                    float aa = a2s[c0], ab = a2s[c0 + 1];
                    v0 += dicef(acc2[nt][0], aa) * wa + dicef(acc2[nt][1], ab) * wb3;
                    v1 += dicef(acc2[nt][2], aa) * wa + dicef(acc2[nt][3], ab) * wb3;
                }
                v0 += __shfl_xor_sync(0xffffffffu, v0, 1);
                v0 += __shfl_xor_sync(0xffffffffu, v0, 2);
                v1 += __shfl_xor_sync(0xffffffffu, v1, 1);
                v1 += __shfl_xor_sync(0xffffffffu, v1, 2);
                if (tig == 0) {
                    int trow0 = t0 + m0 + g;
                    int trow1 = trow0 + 8;
                    if (trow0 < L) g_att[(size_t)trow0 * B + b] = sigt(v0);
                    if (trow1 < L) g_att[(size_t)trow1 * B + b] = sigt(v1);
                }
            } else {
                // ---- warps 2-7: coalesced copy xout -> g_xproj ----
                int idx = tid - 64;          // 0..191
                int r = idx / 6, c = idx % 6;
                int t = t0 + r;
                if (t < L) {
                    size_t gb = ((size_t)t * B + p) * 192;
                    #pragma unroll
                    for (int k = 0; k < 8; k++) {
                        uint4 v = *(uint4*)&xout[r * 196 + c * 4 + k * 24];
                        *(uint4*)&g_xproj[gb + c * 4 + k * 24] = v;
                    }
                }
            }
            __syncthreads();
        }
    }
}

// ---------------- AUGRU scan ----------------
__global__ __launch_bounds__(256) void k_augru(
    const int* __restrict__ slen,
    const float* __restrict__ Wu, const float* __restrict__ Wr, const float* __restrict__ Wc,
    float* __restrict__ out)
{
    extern __shared__ unsigned smw[];
    unsigned* hT  = smw + 24576;
    unsigned* rhT = smw + 26624;
    __shared__ int   Ls[32];
    __shared__ int   bis[32];
    __shared__ float atts[2][32];
    __shared__ int   LmaxS;

    int tid = threadIdx.x;

    for (int e = tid; e < 8192; e += 256) {
        int n = e & 127, kw = e >> 7;
        int sw = n * 64 + (kw ^ ((n & 7) << 2));
        smw[sw]         = packh2(Wu[16384 + (2 * kw) * 128 + n], Wu[16384 + (2 * kw + 1) * 128 + n]);
        smw[8192 + sw]  = packh2(Wr[16384 + (2 * kw) * 128 + n], Wr[16384 + (2 * kw + 1) * 128 + n]);
        smw[16384 + sw] = packh2(Wc[16384 + (2 * kw) * 128 + n], Wc[16384 + (2 * kw + 1) * 128 + n]);
    }
    for (int e = tid; e < 4096; e += 256) hT[e] = 0u;
    if (tid < 32) {
        int b = g_perm[blockIdx.x * 32 + tid];
        bis[tid] = b;
        int L = slen[b]; L = min(max(L, 0), T);
        Ls[tid] = L;
    }
    __syncthreads();
    if (tid == 0) { int m = 0; for (int i = 0; i < 32; i++) m = max(m, Ls[i]); LmaxS = m; }

    const int w = tid >> 5, lane = tid & 31, g = lane >> 2, tig = lane & 3;
    const int gsw = g << 2;
    const int n0w = w * 16;

    unsigned wu[2][8][2], wr[2][8][2], wc[2][8][2];
    #pragma unroll
    for (int nt = 0; nt < 2; nt++) {
        int nb = (n0w + nt * 8 + g) * 64;
        #pragma unroll
        for (int s = 0; s < 8; s++) {
            int k0 = (s * 8 + tig) ^ gsw, k1 = (s * 8 + tig + 4) ^ gsw;
            wu[nt][s][0] = smw[nb + k0];          wu[nt][s][1] = smw[nb + k1];
            wr[nt][s][0] = smw[8192 + nb + k0];   wr[nt][s][1] = smw[8192 + nb + k1];
            wc[nt][s][0] = smw[16384 + nb + k0];  wc[nt][s][1] = smw[16384 + nb + k1];
        }
    }
    __syncthreads();
    const int Lmax = LmaxS;
    const int p0 = blockIdx.x * 32;

    const int sub = lane >> 3, r8 = lane & 7;
    const int hi = sub >> 1;
    const int rsel = (sub & 1) * 8 + r8;
    unsigned hTsa = (unsigned)__cvta_generic_to_shared(hT);
    unsigned baseA[2];
    baseA[0] = hTsa + (unsigned)(rsel * 256);
    baseA[1] = hTsa + (unsigned)((16 + rsel) * 256);

    int stoff[2];
    #pragma unroll
    for (int nt = 0; nt < 2; nt++) stoff[nt] = (((w * 2 + nt) ^ g) << 2) + tig;

    int myL[4];
    #pragma unroll
    for (int ri = 0; ri < 4; ri++) myL[ri] = Ls[(ri >> 1) * 16 + (ri & 1) * 8 + g];

    float hm[2][2][4];
    #pragma unroll
    for (int mt = 0; mt < 2; mt++)
        #pragma unroll
        for (int nt = 0; nt < 2; nt++)
            #pragma unroll
            for (int k = 0; k < 4; k++) hm[mt][nt][k] = 0.0f;

    const int coff = (w * 4 + tig) * 6;   // contiguous 6-word run per (row)

    // preload all-gate x-projections for t=0 and atts[0]
    unsigned xal[2][2][2][3];
    {
        #pragma unroll
        for (int mt = 0; mt < 2; mt++)
            #pragma unroll
            for (int half = 0; half < 2; half++) {
                size_t rb = ((size_t)p0 + mt * 16 + half * 8 + g) * 192 + coff;
                uint2 v0 = *(const uint2*)&g_xproj[rb];
                uint2 v1 = *(const uint2*)&g_xproj[rb + 2];
                uint2 v2 = *(const uint2*)&g_xproj[rb + 4];
                xal[mt][half][0][0] = v0.x; xal[mt][half][1][0] = v0.y;
                xal[mt][half][0][1] = v1.x; xal[mt][half][1][1] = v1.y;
                xal[mt][half][0][2] = v2.x; xal[mt][half][1][2] = v2.y;
            }
        if (tid < 32) atts[0][tid] = g_att[(size_t)0 * B + bis[tid]];
    }
    __syncthreads();

    for (int t = 0; t < Lmax; t++) {
        int cur = t & 1, nxt = cur ^ 1;
        int tn = min(t + 1, T - 1);

        unsigned xaln[2][2][2][3];
        {
            size_t tbn = (size_t)tn * B + p0;
            #pragma unroll
            for (int mt = 0; mt < 2; mt++)
                #pragma unroll
                for (int half = 0; half < 2; half++) {
                    size_t rbn = (tbn + mt * 16 + half * 8 + g) * 192 + coff;
                    uint2 v0 = *(const uint2*)&g_xproj[rbn];
                    uint2 v1 = *(const uint2*)&g_xproj[rbn + 2];
                    uint2 v2 = *(const uint2*)&g_xproj[rbn + 4];
                    xaln[mt][half][0][0] = v0.x; xaln[mt][half][1][0] = v0.y;
                    xaln[mt][half][0][1] = v1.x; xaln[mt][half][1][1] = v1.y;
                    xaln[mt][half][0][2] = v2.x; xaln[mt][half][1][2] = v2.y;
                }
        }
        float attn_v = 0.0f;
        if (tid < 32) attn_v = g_att[(size_t)tn * B + bis[tid]];

        // phase A
        float accU[2][2][4], accR[2][2][4];
        #pragma unroll
        for (int mt = 0; mt < 2; mt++)
            #pragma unroll
            for (int nt = 0; nt < 2; nt++)
                #pragma unroll
                for (int k = 0; k < 4; k++) { accU[mt][nt][k] = 0.0f; accR[mt][nt][k] = 0.0f; }

        #pragma unroll
        for (int s = 0; s < 8; s++) {
            unsigned choff = (unsigned)((((2 * s + hi) ^ r8) << 4));
            unsigned ah[2][4];
            ldsm_x4(ah[0], baseA[0] + choff);
            ldsm_x4(ah[1], baseA[1] + choff);
            #pragma unroll
            for (int nt = 0; nt < 2; nt++)
                #pragma unroll
                for (int mt = 0; mt < 2; mt++) {
                    mma_f16(accU[mt][nt], ah[mt], wu[nt][s]);
                    mma_f16(accR[mt][nt], ah[mt], wr[nt][s]);
                }
        }

        // gates u, r; store r*h
        float uu[2][2][4];
        #pragma unroll
        for (int mt = 0; mt < 2; mt++)
            #pragma unroll
            for (int nt = 0; nt < 2; nt++)
                #pragma unroll
                for (int half = 0; half < 2; half++) {
                    int row = mt * 16 + half * 8 + g;
                    float2 xu = unpackh2(xal[mt][half][nt][0]);
                    float2 xr = unpackh2(xal[mt][half][nt][1]);
                    float2 uv = sig2(accU[mt][nt][half * 2 + 0] + xu.x, accU[mt][nt][half * 2 + 1] + xu.y);
                    float2 rv = sig2(accR[mt][nt][half * 2 + 0] + xr.x, accR[mt][nt][half * 2 + 1] + xr.y);
                    uu[mt][nt][half * 2 + 0] = uv.x;
                    uu[mt][nt][half * 2 + 1] = uv.y;
                    rhT[row * 64 + stoff[nt]] =
                        packh2(rv.x * hm[mt][nt][half * 2 + 0], rv.y * hm[mt][nt][half * 2 + 1]);
                }
        if (tid < 32) atts[nxt][tid] = attn_v;
        __syncthreads();

        // phase B
        float accC[2][2][4];
        #pragma unroll
        for (int mt = 0; mt < 2; mt++)
            #pragma unroll
            for (int nt = 0; nt < 2; nt++)
                #pragma unroll
                for (int half = 0; half < 2; half++) {
                    float2 xc = unpackh2(xal[mt][half][nt][2]);
                    accC[mt][nt][half * 2 + 0] = xc.x;
                    accC[mt][nt][half * 2 + 1] = xc.y;
                }

        #pragma unroll
        for (int s = 0; s < 8; s++) {
            unsigned choff = (unsigned)((((2 * s + hi) ^ r8) << 4)) + 8192u;
            unsigned ar[2][4];
            ldsm_x4(ar[0], baseA[0] + choff);
            ldsm_x4(ar[1], baseA[1] + choff);
            #pragma unroll
            for (int nt = 0; nt < 2; nt++)
                #pragma unroll
                for (int mt = 0; mt < 2; mt++)
                    mma_f16(accC[mt][nt], ar[mt], wc[nt][s]);
        }

        // h update + refresh hT
        #pragma unroll
        for (int mt = 0; mt < 2; mt++)
            #pragma unroll
            for (int nt = 0; nt < 2; nt++)
                #pragma unroll
                for (int half = 0; half < 2; half++) {
                    int ri = mt * 2 + half;
                    int row = mt * 16 + half * 8 + g;
                    if (t < myL[ri]) {
                        float a_att = atts[cur][row];
                        float c0 = tanha(accC[mt][nt][half * 2 + 0]);
                        float c1 = tanha(accC[mt][nt][half * 2 + 1]);
                        float ut0 = uu[mt][nt][half * 2 + 0] * a_att;
                        float ut1 = uu[mt][nt][half * 2 + 1] * a_att;
                        hm[mt][nt][half * 2 + 0] += ut0 * (c0 - hm[mt][nt][half * 2 + 0]);
                        hm[mt][nt][half * 2 + 1] += ut1 * (c1 - hm[mt][nt][half * 2 + 1]);
                    }
                    hT[row * 64 + stoff[nt]] =
                        packh2(hm[mt][nt][half * 2 + 0], hm[mt][nt][half * 2 + 1]);
                }
        __syncthreads();

        #pragma unroll
        for (int mt = 0; mt < 2; mt++)
            #pragma unroll
            for (int half = 0; half < 2; half++)
                #pragma unroll
                for (int nt = 0; nt < 2; nt++)
                    #pragma unroll
                    for (int gt = 0; gt < 3; gt++)
                        xal[mt][half][nt][gt] = xaln[mt][half][nt][gt];
    }

    #pragma unroll
    for (int mt = 0; mt < 2; mt++)
        #pragma unroll
        for (int nt = 0; nt < 2; nt++) {
            int col = n0w + nt * 8 + tig * 2;
            #pragma unroll
            for (int half = 0; half < 2; half++) {
                int row = mt * 16 + half * 8 + g;
                size_t base = (size_t)bis[row] * U + col;
                out[base]     = hm[mt][nt][half * 2 + 0];
                out[base + 1] = hm[mt][nt][half * 2 + 1];
            }
        }
}

// ---------------- launch ----------------
extern "C" void kernel_launch(void* const* d_in, const int* in_sizes, int n_in,
                              void* d_out, int out_size)
{
    const float* x    = (const float*)d_in[0];
    const float* q    = (const float*)d_in[1];
    const int*   slen = (const int*)d_in[2];
    const float* W1   = (const float*)d_in[3];
    const float* a1   = (const float*)d_in[4];
    const float* W2   = (const float*)d_in[5];
    const float* a2   = (const float*)d_in[6];
    const float* W3   = (const float*)d_in[7];
    const float* Wu   = (const float*)d_in[8];
    const float* Wr   = (const float*)d_in[9];
    const float* Wc   = (const float*)d_in[10];
    float* out = (float*)d_out;

    const int FUSED_SMEM = 24576 * 4;
    const int AUGRU_SMEM = 28672 * 4;

    cudaFuncSetAttribute(k_fused, cudaFuncAttributeMaxDynamicSharedMemorySize, FUSED_SMEM);
    cudaFuncSetAttribute(k_augru, cudaFuncAttributeMaxDynamicSharedMemorySize, AUGRU_SMEM);

    k_sort<<<1, 512>>>(slen);
    k_fused<<<512, 256, FUSED_SMEM>>>(x, q, slen, W1, a1, W2, a2, W3, Wu, Wr, Wc);
    k_augru<<<B / 32, 256, AUGRU_SMEM>>>(slen, Wu, Wr, Wc, out);
}